// round 1
// baseline (speedup 1.0000x reference)
#include <cuda_runtime.h>
#include <math.h>

#define GROUP_SIZE 32

// Scratch (device globals per allocation rules). Max 4096 groups supported.
__device__ unsigned int g_maxbits[4096];
__device__ float4       g_se[4096];   // (scale, 1/scale, eps_eff, unused)

// ---------------------------------------------------------------------------
// Kernel 0: zero the max scratch (required for deterministic graph replay)
// ---------------------------------------------------------------------------
__global__ void k_init(int G) {
    int g = blockIdx.x * blockDim.x + threadIdx.x;
    if (g < G) g_maxbits[g] = 0u;
}

// ---------------------------------------------------------------------------
// Kernel 1: per-group max|w| reduction.
// Each thread owns one float4-column (group fixed), slabs of rows per block.y.
// ---------------------------------------------------------------------------
__global__ void k_max(const float4* __restrict__ w, int C4, int rows_per, int R) {
    int c4 = blockIdx.x * blockDim.x + threadIdx.x;
    if (c4 >= C4) return;
    int r0 = blockIdx.y * rows_per;
    int r_end = R - r0;
    if (r_end > rows_per) r_end = rows_per;

    const float4* p = w + (size_t)r0 * C4 + c4;
    float m = 0.0f;
#pragma unroll 4
    for (int r = 0; r < r_end; r++) {
        float4 v = p[(size_t)r * C4];
        float a = fmaxf(fmaxf(fabsf(v.x), fabsf(v.y)),
                        fmaxf(fabsf(v.z), fabsf(v.w)));
        m = fmaxf(m, a);
    }
    // 8 consecutive lanes share a group (group = c4 >> 3): butterfly reduce
    m = fmaxf(m, __shfl_xor_sync(0xffffffffu, m, 1));
    m = fmaxf(m, __shfl_xor_sync(0xffffffffu, m, 2));
    m = fmaxf(m, __shfl_xor_sync(0xffffffffu, m, 4));
    if ((threadIdx.x & 7) == 0) {
        // |w| >= 0 so float bit pattern ordering == unsigned int ordering
        atomicMax(&g_maxbits[c4 >> 3], __float_as_uint(m));
    }
}

// ---------------------------------------------------------------------------
// Kernel 2: per-group scalars: e_base (exact via ilogbf), scale, eps_eff.
// Also writes the two small output tails.
// ---------------------------------------------------------------------------
__global__ void k_mid(const float* __restrict__ eps_param,
                      const float* __restrict__ delta,
                      float* __restrict__ out, long long RL, int G) {
    int g = blockIdx.x * blockDim.x + threadIdx.x;
    if (g >= G) return;
    float ma = __uint_as_float(g_maxbits[g]);
    float e  = (ma > 0.0f) ? (float)ilogbf(ma) : 0.0f;  // exact floor(log2)
    float s  = exp2f(e);                                 // exact power of two
    float ev = 0.5f * tanhf(eps_param[g]);
    float ee = fminf(fmaxf(ev + delta[g], -0.5f), 0.5f);
    g_se[g] = make_float4(s, 1.0f / s, ee, 0.0f);
    out[RL + g]     = ee;   // eps_eff
    out[RL + G + g] = e;    // e_base
}

// ---------------------------------------------------------------------------
// Kernel 3: quantize. float4 in / float4 out, 4 independent iters per thread.
// ---------------------------------------------------------------------------
__device__ __forceinline__ float qone(float x, float s, float inv, float ee) {
    float a  = fabsf(x);
    float r  = fminf(a * inv, 1.0f);
    float sh = fminf(fmaxf(r + ee, 0.0f), 1.0f);
    float mq = rintf(sh * 8.0f) * 0.125f;   // half-to-even, matches jnp.round
    float q  = copysignf(s * mq, x);
    return (x == 0.0f) ? 0.0f : q;          // jnp.sign(0) == 0
}

__global__ void k_quant(const float4* __restrict__ w, float4* __restrict__ out,
                        long long n4, int c4mask) {
    long long stride = (long long)gridDim.x * blockDim.x;
    long long i0 = (long long)blockIdx.x * blockDim.x + threadIdx.x;
#pragma unroll
    for (int k = 0; k < 4; k++) {
        long long j = i0 + (long long)k * stride;
        if (j < n4) {
            float4 v  = w[j];
            int   g   = (((int)j) & c4mask) >> 3;  // (j % C4) / 8
            float4 se = g_se[g];
            float4 o;
            o.x = qone(v.x, se.x, se.y, se.z);
            o.y = qone(v.y, se.x, se.y, se.z);
            o.z = qone(v.z, se.x, se.y, se.z);
            o.w = qone(v.w, se.x, se.y, se.z);
            out[j] = o;
        }
    }
}

// ---------------------------------------------------------------------------
// Launch
// ---------------------------------------------------------------------------
extern "C" void kernel_launch(void* const* d_in, const int* in_sizes, int n_in,
                              void* d_out, int out_size) {
    const float* w     = (const float*)d_in[0];
    const float* epsp  = (const float*)d_in[1];
    const float* delta = (const float*)d_in[2];
    float* out = (float*)d_out;

    long long RL = (long long)in_sizes[0];      // 4096 * 16384
    int G  = in_sizes[1];                       // 512
    int L  = G * GROUP_SIZE;                    // 16384
    int R  = (int)(RL / L);                     // 4096
    int C4 = L / 4;                             // 4096 float4 per row

    // init scratch
    k_init<<<(G + 255) / 256, 256>>>(G);

    // pass 1: per-group max-abs
    int slabs = 64;
    int rows_per = (R + slabs - 1) / slabs;
    dim3 g1((C4 + 255) / 256, slabs);
    k_max<<<g1, 256>>>((const float4*)w, C4, rows_per, R);

    // per-group scalars + small outputs
    k_mid<<<(G + 255) / 256, 256>>>(epsp, delta, out, RL, G);

    // pass 2: quantize
    long long n4 = RL / 4;
    long long threads_needed = (n4 + 3) / 4;
    int blocks = (int)((threads_needed + 255) / 256);
    k_quant<<<blocks, 256>>>((const float4*)w, (float4*)out, n4, C4 - 1);
}